// round 14
// baseline (speedup 1.0000x reference)
#include <cuda_runtime.h>
#include <cuda_fp16.h>
#include <cstdint>

#define NMAX 100000
#define EMAX 1600000
#define HDIM 128
#define SCAN_B 256

// ---------------- scratch (device globals) ----------------------------------
__device__ float g_T[NMAX * HDIM];     // fp16 T ping
__device__ float g_A[NMAX * HDIM];     // fp16 H ping
__device__ float g_B[NMAX * HDIM];     // fp16 H pong; ALSO int2 edge temp during CSR build
__device__ float g_dinv[NMAX];
__device__ float g_selfc[NMAX];        // 1/deg (self-loop coefficient)
__device__ int   g_count[NMAX + 32];   // padded for vector init
__device__ int   g_rowptr[NMAX + 1];
__device__ int   g_cursor[NMAX];
__device__ int   g_bsum[512];
__device__ int2  g_edges[EMAX];        // packed (src, coef-bits), dst-grouped
__device__ unsigned int g_Wph[3 * 8192]; // W2|W3|W4 prepacked into B-frag layout
__device__ int   g_edge64;
__device__ int   g_batch64;

// ---------------- dtype detection (int64 vs int32) ---------------------------
__global__ void detect_kernel(const int* __restrict__ ei32,
                              const int* __restrict__ b32, int nb) {
    if (threadIdx.x != 0) return;
    int nz = 0;
#pragma unroll
    for (int i = 1; i < 17; i += 2) nz |= ei32[i];
    g_edge64 = (nz == 0) ? 1 : 0;
    nz = 0;
    for (int k = 0; k < 16; k++) {
        int j = nb - 1 - k;
        if (j >= 1 && (j & 1)) nz |= b32[j];
    }
    g_batch64 = (nz == 0) ? 1 : 0;
}

__device__ __forceinline__ void load_edge(const void* ei, int E, int e, int& s, int& d) {
    if (g_edge64) {
        const long long* p = (const long long*)ei;
        s = (int)p[e]; d = (int)p[E + e];
    } else {
        const int* p = (const int*)ei;
        s = p[e]; d = p[E + e];
    }
}

// ---------------- CSR build --------------------------------------------------
__global__ void count_init_kernel(int n4) {     // n4 = ceil(n/4)
    int i = blockIdx.x * blockDim.x + threadIdx.x;
    if (i < n4) ((int4*)g_count)[i] = make_int4(0, 0, 0, 0);
}

// count + compact edges to int2 temp (tmp aliases g_B; dead until layer-2 gather)
__global__ void count_kernel(const void* __restrict__ ei, int2* __restrict__ tmp, int E) {
    int e = blockIdx.x * blockDim.x + threadIdx.x;
    if (e >= E) return;
    int s, d; load_edge(ei, E, e, s, d);
    atomicAdd(&g_count[d], 1);
    tmp[e] = make_int2(s, d);
}

// block-local exclusive scan of counts; dinv/selfc fused here
__global__ void scan_block_kernel(int n) {
    __shared__ int sh[SCAN_B];
    int tid = threadIdx.x;
    int i = blockIdx.x * SCAN_B + tid;
    int v = (i < n) ? g_count[i] : 0;
    if (i < n) {
        float deg = (float)(v + 1);        // + self-loop
        g_dinv[i] = rsqrtf(deg);
        g_selfc[i] = 1.0f / deg;
    }
    sh[tid] = v;
    __syncthreads();
#pragma unroll
    for (int off = 1; off < SCAN_B; off <<= 1) {
        int t = (tid >= off) ? sh[tid - off] : 0;
        __syncthreads();
        sh[tid] += t;
        __syncthreads();
    }
    if (i < n) g_rowptr[i] = sh[tid] - v;
    if (tid == SCAN_B - 1) g_bsum[blockIdx.x] = sh[tid];
}

// fused top-level scan + add: each block reduces bsum[0..bid) itself
__global__ void scan_add_kernel(int n, int E) {
    __shared__ int red[SCAN_B];
    int bid = blockIdx.x;
    int tid = threadIdx.x;
    int s = 0;
    for (int j = tid; j < bid; j += SCAN_B) s += g_bsum[j];
    red[tid] = s;
    __syncthreads();
#pragma unroll
    for (int off = SCAN_B / 2; off > 0; off >>= 1) {
        if (tid < off) red[tid] += red[tid + off];
        __syncthreads();
    }
    int boff = red[0];
    int i = bid * SCAN_B + tid;
    if (i < n) {
        int r = g_rowptr[i] + boff;
        g_rowptr[i] = r;
        g_cursor[i] = r;
    }
    if (i == 0) g_rowptr[n] = E;
}

// fill from the compacted int2 temp (12.8MB read instead of 25.6MB int64)
__global__ void fill_kernel(const int2* __restrict__ tmp, int E) {
    int e = blockIdx.x * blockDim.x + threadIdx.x;
    if (e >= E) return;
    int2 sd = tmp[e];
    float c = g_dinv[sd.x] * g_dinv[sd.y];
    int idx = atomicAdd(&g_cursor[sd.y], 1);
    g_edges[idx] = make_int2(sd.x, __float_as_int(c));
}

// ------- fused layer 1: H1 = relu((A_norm x) @ W1 + b1) -> fp16 ---------------
// one warp per node: lanes split edges, shfl-reduce z[4], each lane emits 4 feats
__global__ void layer1_kernel(const float* __restrict__ x, const float* __restrict__ W,
                              const float* __restrict__ b, __half* __restrict__ Hout,
                              int n) {
    __shared__ float Ws[4 * 128 + 128];
    for (int i = threadIdx.x; i < 512; i += blockDim.x) Ws[i] = W[i];
    for (int i = threadIdx.x; i < 128; i += blockDim.x) Ws[512 + i] = b[i];
    __syncthreads();

    int warp = threadIdx.x >> 5;
    int lane = threadIdx.x & 31;
    int node = blockIdx.x * 8 + warp;
    if (node >= n) return;

    const float4* x4 = (const float4*)x;
    float4 acc = make_float4(0.f, 0.f, 0.f, 0.f);
    int lo = g_rowptr[node], hi = g_rowptr[node + 1];
    for (int e = lo + lane; e < hi; e += 32) {
        int2 ed = g_edges[e];
        float c = __int_as_float(ed.y);
        float4 v = __ldg(&x4[ed.x]);
        acc.x += c * v.x; acc.y += c * v.y; acc.z += c * v.z; acc.w += c * v.w;
    }
#pragma unroll
    for (int off = 16; off > 0; off >>= 1) {
        acc.x += __shfl_down_sync(0xffffffffu, acc.x, off);
        acc.y += __shfl_down_sync(0xffffffffu, acc.y, off);
        acc.z += __shfl_down_sync(0xffffffffu, acc.z, off);
        acc.w += __shfl_down_sync(0xffffffffu, acc.w, off);
    }
    float4 xv = x4[node];
    float sc = g_selfc[node];
    float zx = __shfl_sync(0xffffffffu, acc.x, 0) + sc * xv.x;
    float zy = __shfl_sync(0xffffffffu, acc.y, 0) + sc * xv.y;
    float zz = __shfl_sync(0xffffffffu, acc.z, 0) + sc * xv.z;
    float zw = __shfl_sync(0xffffffffu, acc.w, 0) + sc * xv.w;

    int f0 = lane * 4;
    float o[4];
#pragma unroll
    for (int q = 0; q < 4; q++) {
        int f = f0 + q;
        o[q] = Ws[512 + f] + zx * Ws[f] + zy * Ws[128 + f]
             + zz * Ws[256 + f] + zw * Ws[384 + f];
    }
    __half2 h0 = __floats2half2_rn(fmaxf(o[0], 0.f), fmaxf(o[1], 0.f));
    __half2 h1 = __floats2half2_rn(fmaxf(o[2], 0.f), fmaxf(o[3], 0.f));
    uint2 ou;
    ou.x = *(unsigned*)&h0;
    ou.y = *(unsigned*)&h1;
    ((uint2*)Hout)[(size_t)node * 32 + lane] = ou;
}

// ---------------- fp16 mma helper --------------------------------------------
__device__ __forceinline__ void mma_fp16(float& c0, float& c1, float& c2, float& c3,
                                         unsigned a0, unsigned a1, unsigned a2, unsigned a3,
                                         unsigned b0, unsigned b1) {
    asm volatile("mma.sync.aligned.m16n8k16.row.col.f32.f16.f16.f32 "
                 "{%0,%1,%2,%3}, {%4,%5,%6,%7}, {%8,%9}, {%0,%1,%2,%3};"
                 : "+f"(c0), "+f"(c1), "+f"(c2), "+f"(c3)
                 : "r"(a0), "r"(a1), "r"(a2), "r"(a3), "r"(b0), "r"(b1));
}

// ---------------- W prepack (all 3 layers in one kernel) ----------------------
__global__ void prepack_all_kernel(const float* __restrict__ W2,
                                   const float* __restrict__ W3,
                                   const float* __restrict__ W4) {
    int idx = blockIdx.x * blockDim.x + threadIdx.x;
    if (idx >= 3 * 8192) return;
    const float* W = (idx < 8192) ? W2 : (idx < 16384) ? W3 : W4;
    int li   = idx & 8191;
    int r    = li & 1;
    int nt   = (li >> 1) & 3;
    int lane = (li >> 3) & 31;
    int wn   = (li >> 8) & 3;
    int kt   = li >> 10;                   // 0..7
    int k    = 16 * kt + 2 * (lane & 3) + 8 * r;
    int ncol = wn * 32 + nt * 8 + (lane >> 2);
    __half2 h = __floats2half2_rn(W[k * 128 + ncol], W[(k + 1) * 128 + ncol]);
    g_Wph[idx] = *(unsigned*)&h;
}

// ---------------- layers 2..4 matmul: T = Hin(fp16) @ W  (fp16 HMMA) ---------
#define MM_SMEM (128 * 136 * 2 + 8192 * 4)
__global__ void __launch_bounds__(256, 2) mm_tc_kernel(const __half* __restrict__ Hin,
                                                       const unsigned* __restrict__ Wsrc,
                                                       __half* __restrict__ T, int n) {
    extern __shared__ char smem[];
    __half* As = (__half*)smem;
    unsigned* Ws = (unsigned*)(smem + 128 * 136 * 2);

    int tid = threadIdx.x;
    int row0 = blockIdx.x * 128;

    {
        const uint4* H4 = (const uint4*)Hin;        // 16 uint4 per row
        for (int i = tid; i < 128 * 16; i += 256) {
            int r = i >> 4;
            int c = i & 15;
            int gr = row0 + r;
            uint4 v = make_uint4(0u, 0u, 0u, 0u);
            if (gr < n) v = H4[(size_t)gr * 16 + c];
            *(uint4*)(As + r * 136 + c * 8) = v;
        }
        uint4* Wd = (uint4*)Ws;
        const uint4* Wsc = (const uint4*)Wsrc;
        for (int i = tid; i < 2048; i += 256) Wd[i] = Wsc[i];
    }
    __syncthreads();

    int warp = tid >> 5;
    int lane = tid & 31;
    int wm = warp >> 2;            // 0..1
    int wn = warp & 3;             // 0..3

    float acc[4][4][4];
#pragma unroll
    for (int mt = 0; mt < 4; mt++)
#pragma unroll
        for (int nt = 0; nt < 4; nt++)
#pragma unroll
            for (int r = 0; r < 4; r++) acc[mt][nt][r] = 0.f;

    int arow = lane & 15;
    int acol = (lane >> 4) << 3;

    const uint4* WB = (const uint4*)Ws;
#pragma unroll
    for (int kt = 0; kt < 8; kt++) {
        unsigned a[4][4];
#pragma unroll
        for (int mt = 0; mt < 4; mt++) {
            const __half* p = As + (wm * 64 + mt * 16 + arow) * 136 + kt * 16 + acol;
            unsigned addr = (unsigned)__cvta_generic_to_shared(p);
            asm volatile("ldmatrix.sync.aligned.m8n8.x4.shared.b16 {%0,%1,%2,%3}, [%4];"
                         : "=r"(a[mt][0]), "=r"(a[mt][1]), "=r"(a[mt][2]), "=r"(a[mt][3])
                         : "r"(addr));
        }
        int wbase = (((kt * 4 + wn) * 32 + lane) * 8) >> 2;   // uint4 index
        uint4 w0 = WB[wbase];
        uint4 w1 = WB[wbase + 1];
        unsigned b[4][2] = {{w0.x, w0.y}, {w0.z, w0.w}, {w1.x, w1.y}, {w1.z, w1.w}};
#pragma unroll
        for (int mt = 0; mt < 4; mt++)
#pragma unroll
            for (int nt = 0; nt < 4; nt++)
                mma_fp16(acc[mt][nt][0], acc[mt][nt][1], acc[mt][nt][2], acc[mt][nt][3],
                         a[mt][0], a[mt][1], a[mt][2], a[mt][3], b[nt][0], b[nt][1]);
    }

    // epilogue: convert to half2, write T
    int l4 = lane >> 2;
    int lm4 = lane & 3;
#pragma unroll
    for (int mt = 0; mt < 4; mt++) {
        int row = row0 + wm * 64 + mt * 16 + l4;
#pragma unroll
        for (int nt = 0; nt < 4; nt++) {
            int col = wn * 32 + nt * 8 + 2 * lm4;
            if (row < n) {
                __half2 h = __floats2half2_rn(acc[mt][nt][0], acc[mt][nt][1]);
                *(unsigned*)&T[(size_t)row * 128 + col] = *(unsigned*)&h;
            }
            if (row + 8 < n) {
                __half2 h = __floats2half2_rn(acc[mt][nt][2], acc[mt][nt][3]);
                *(unsigned*)&T[(size_t)(row + 8) * 128 + col] = *(unsigned*)&h;
            }
        }
    }
}

// ------- CSR gather: Hout[i] = relu(b + selfc*T[i] + sum coef*T[src]) (fp16) -
// R7-exact structure: 8/4/1 unroll tiers (measured best); __ldg on T reads.
__global__ void gather_kernel(const __half* __restrict__ T, const float* __restrict__ b,
                              __half* __restrict__ Hout, int n) {
    int node = blockIdx.x * 8 + (threadIdx.x >> 5);
    if (node >= n) return;
    int lane = threadIdx.x & 31;
    const uint2* T2 = (const uint2*)T;       // 4 halves per lane; row stride 32

    float4 acc;
    {
        uint2 raw = __ldg(&T2[(size_t)node * 32 + lane]);
        float2 f0 = __half22float2(*(__half2*)&raw.x);
        float2 f1 = __half22float2(*(__half2*)&raw.y);
        float sc = g_selfc[node];
        acc = make_float4(f0.x * sc, f0.y * sc, f1.x * sc, f1.y * sc);
    }

    int lo = g_rowptr[node], hi = g_rowptr[node + 1];
    for (int base = lo; base < hi; base += 32) {
        int e = base + lane;
        int s = 0; float c = 0.f;
        if (e < hi) {
            int2 ed = g_edges[e];
            s = ed.x; c = __int_as_float(ed.y);
        }
        int cnt = min(32, hi - base);
        int j = 0;
        for (; j + 8 <= cnt; j += 8) {
            int sa[8]; float ca[8]; uint2 rw[8];
#pragma unroll
            for (int q = 0; q < 8; q++) {
                sa[q] = __shfl_sync(0xffffffffu, s, j + q);
                ca[q] = __shfl_sync(0xffffffffu, c, j + q);
            }
#pragma unroll
            for (int q = 0; q < 8; q++) rw[q] = __ldg(&T2[(size_t)sa[q] * 32 + lane]);
#pragma unroll
            for (int q = 0; q < 8; q++) {
                float2 f0 = __half22float2(*(__half2*)&rw[q].x);
                float2 f1 = __half22float2(*(__half2*)&rw[q].y);
                acc.x += ca[q] * f0.x; acc.y += ca[q] * f0.y;
                acc.z += ca[q] * f1.x; acc.w += ca[q] * f1.y;
            }
        }
        for (; j + 4 <= cnt; j += 4) {
            int sa[4]; float ca[4]; uint2 rw[4];
#pragma unroll
            for (int q = 0; q < 4; q++) {
                sa[q] = __shfl_sync(0xffffffffu, s, j + q);
                ca[q] = __shfl_sync(0xffffffffu, c, j + q);
            }
#pragma unroll
            for (int q = 0; q < 4; q++) rw[q] = __ldg(&T2[(size_t)sa[q] * 32 + lane]);
#pragma unroll
            for (int q = 0; q < 4; q++) {
                float2 f0 = __half22float2(*(__half2*)&rw[q].x);
                float2 f1 = __half22float2(*(__half2*)&rw[q].y);
                acc.x += ca[q] * f0.x; acc.y += ca[q] * f0.y;
                acc.z += ca[q] * f1.x; acc.w += ca[q] * f1.y;
            }
        }
        for (; j < cnt; j++) {
            int   ss = __shfl_sync(0xffffffffu, s, j);
            float cc = __shfl_sync(0xffffffffu, c, j);
            uint2 r = __ldg(&T2[(size_t)ss * 32 + lane]);
            float2 f0 = __half22float2(*(__half2*)&r.x);
            float2 f1 = __half22float2(*(__half2*)&r.y);
            acc.x += cc*f0.x; acc.y += cc*f0.y; acc.z += cc*f1.x; acc.w += cc*f1.y;
        }
    }
    float4 bv = ((const float4*)b)[lane];
    __half2 h0 = __floats2half2_rn(fmaxf(acc.x + bv.x, 0.f), fmaxf(acc.y + bv.y, 0.f));
    __half2 h1 = __floats2half2_rn(fmaxf(acc.z + bv.z, 0.f), fmaxf(acc.w + bv.w, 0.f));
    uint2 o;
    o.x = *(unsigned*)&h0;
    o.y = *(unsigned*)&h1;
    ((uint2*)Hout)[(size_t)node * 32 + lane] = o;
}

// ---------------- pool (fp16 in, relu'd already) + head ----------------------
__device__ __forceinline__ long long batch_val(const void* b, int i, int is64) {
    return is64 ? ((const long long*)b)[i] : (long long)((const int*)b)[i];
}
__device__ __forceinline__ int lb_batch(const void* b, int n, int is64, long long key) {
    int lo = 0, hi = n;
    while (lo < hi) {
        int mid = (lo + hi) >> 1;
        if (batch_val(b, mid, is64) < key) lo = mid + 1; else hi = mid;
    }
    return lo;
}

__global__ void pool_kernel(const __half* __restrict__ Hf, const void* __restrict__ batch,
                            const float* __restrict__ Wl, const float* __restrict__ bl,
                            float* __restrict__ out, int n) {
    int g = blockIdx.x;
    int is64 = g_batch64;
    int lo = lb_batch(batch, n, is64, (long long)g);
    int hi = lb_batch(batch, n, is64, (long long)g + 1);
    int f = threadIdx.x;              // 0..63, handles half2 pair

    float2 sum = make_float2(0.f, 0.f);
    const __half2* H2 = (const __half2*)Hf;
    for (int i = lo; i < hi; i++) {
        float2 v = __half22float2(H2[(size_t)i * 64 + f]);
        sum.x += v.x; sum.y += v.y;
    }

    float cnt = (float)((hi - lo) > 0 ? (hi - lo) : 1);
    __shared__ float sp[128];
    sp[2 * f]     = sum.x / cnt;
    sp[2 * f + 1] = sum.y / cnt;
    __syncthreads();

    if (f < 5) {
        float a = bl[f];
#pragma unroll 8
        for (int k = 0; k < 128; k++) a += sp[k] * Wl[k * 5 + f];
        out[g * 5 + f] = 1.f / (1.f + expf(-a));
    }
}

// ---------------- launch -----------------------------------------------------
extern "C" void kernel_launch(void* const* d_in, const int* in_sizes, int n_in,
                              void* d_out, int out_size) {
    const float* x  = (const float*)d_in[0];
    const void*  ei = d_in[1];
    const void*  bt = d_in[2];
    const float* W1 = (const float*)d_in[3];
    const float* b1 = (const float*)d_in[4];
    const float* W2 = (const float*)d_in[5];
    const float* b2 = (const float*)d_in[6];
    const float* W3 = (const float*)d_in[7];
    const float* b3 = (const float*)d_in[8];
    const float* W4 = (const float*)d_in[9];
    const float* b4 = (const float*)d_in[10];
    const float* Wl = (const float*)d_in[11];
    const float* bl = (const float*)d_in[12];
    float* out = (float*)d_out;

    int n  = in_sizes[0] / 4;
    int E  = in_sizes[1] / 2;
    int nb = in_sizes[2];
    int G  = out_size / 5;

    float *Tf, *Af, *Bf;
    cudaGetSymbolAddress((void**)&Tf, g_T);
    cudaGetSymbolAddress((void**)&Af, g_A);
    cudaGetSymbolAddress((void**)&Bf, g_B);
    unsigned* Wp;
    cudaGetSymbolAddress((void**)&Wp, g_Wph);
    __half* Th = (__half*)Tf;
    __half* Ah = (__half*)Af;
    __half* Bh = (__half*)Bf;
    int2* tmp = (int2*)Bf;       // edge temp aliases g_B (dead until layer-2 gather)

    cudaFuncSetAttribute(mm_tc_kernel, cudaFuncAttributeMaxDynamicSharedMemorySize, MM_SMEM);

    const int TB = 256;
    int gE  = (E + TB - 1) / TB;
    int gMM = (n + 127) / 128;
    int gGA = (n + 7) / 8;
    int nblk = (n + SCAN_B - 1) / SCAN_B;
    int n4  = (n + 3) / 4;

    // prep + CSR build
    detect_kernel<<<1, 32>>>((const int*)ei, (const int*)bt, nb);
    prepack_all_kernel<<<96, 256>>>(W2, W3, W4);
    count_init_kernel<<<(n4 + TB - 1) / TB, TB>>>(n4);
    count_kernel<<<gE, TB>>>(ei, tmp, E);
    scan_block_kernel<<<nblk, SCAN_B>>>(n);
    scan_add_kernel<<<nblk, SCAN_B>>>(n, E);
    fill_kernel<<<gE, TB>>>(tmp, E);

    // fused layer 1: gather x + mm4 + relu -> fp16 H1 (g_A)
    layer1_kernel<<<gGA, TB>>>(x, W1, b1, Ah, n);

    // layers 2..4: fp16 tensor-core mm + fp16 CSR gather (bias+relu fused)
    mm_tc_kernel<<<gMM, TB, MM_SMEM>>>(Ah, Wp, Th, n);
    gather_kernel<<<gGA, TB>>>(Th, b2, Bh, n);

    mm_tc_kernel<<<gMM, TB, MM_SMEM>>>(Bh, Wp + 8192, Th, n);
    gather_kernel<<<gGA, TB>>>(Th, b3, Ah, n);

    mm_tc_kernel<<<gMM, TB, MM_SMEM>>>(Ah, Wp + 16384, Th, n);
    gather_kernel<<<gGA, TB>>>(Th, b4, Bh, n);

    // pool (mean of relu'd fp16 H4) + head
    pool_kernel<<<G, 64>>>(Bh, bt, Wl, bl, out, n);
}

// round 15
// speedup vs baseline: 1.3388x; 1.3388x over previous
#include <cuda_runtime.h>
#include <cuda_fp16.h>
#include <cstdint>

#define NMAX 100000
#define EMAX 1600000
#define HDIM 128
#define SCAN_B 256

// ---------------- scratch (device globals) ----------------------------------
__device__ float g_T[NMAX * HDIM];     // fp16 T lives here; also z[N,4] temp (fp32)
__device__ float g_A[NMAX * HDIM];     // fp16 H ping
__device__ float g_B[NMAX * HDIM];     // fp16 H pong
__device__ float g_dinv[NMAX];
__device__ float g_selfc[NMAX];        // 1/deg (self-loop coefficient)
__device__ int   g_count[NMAX + 32];   // padded so vector init can overrun safely
__device__ int   g_rowptr[NMAX + 1];
__device__ int   g_cursor[NMAX];
__device__ int   g_bsum[512];
__device__ int2  g_edges[EMAX];        // packed (src, coef-bits)
__device__ unsigned int g_Wph[3 * 8192]; // W2|W3|W4 prepacked into B-frag layout
__device__ int   g_edge64;
__device__ int   g_batch64;

// ---------------- dtype detection (int64 vs int32) ---------------------------
__global__ void detect_kernel(const int* __restrict__ ei32,
                              const int* __restrict__ b32, int nb) {
    if (threadIdx.x != 0) return;
    int nz = 0;
#pragma unroll
    for (int i = 1; i < 17; i += 2) nz |= ei32[i];
    g_edge64 = (nz == 0) ? 1 : 0;
    nz = 0;
    for (int k = 0; k < 16; k++) {
        int j = nb - 1 - k;
        if (j >= 1 && (j & 1)) nz |= b32[j];
    }
    g_batch64 = (nz == 0) ? 1 : 0;
}

__device__ __forceinline__ void load_edge(const void* ei, int E, int e, int& s, int& d) {
    if (g_edge64) {
        const long long* p = (const long long*)ei;
        s = (int)p[e]; d = (int)p[E + e];
    } else {
        const int* p = (const int*)ei;
        s = p[e]; d = p[E + e];
    }
}

// ---------------- CSR build --------------------------------------------------
__global__ void count_init_kernel(int n4) {     // n4 = ceil(n/4)
    int i = blockIdx.x * blockDim.x + threadIdx.x;
    if (i < n4) ((int4*)g_count)[i] = make_int4(0, 0, 0, 0);
}

__global__ void count_kernel(const void* __restrict__ ei, int E) {
    int e = blockIdx.x * blockDim.x + threadIdx.x;
    if (e >= E) return;
    int s, d; load_edge(ei, E, e, s, d);
    atomicAdd(&g_count[d], 1);
}

// block-local exclusive scan of counts; dinv/selfc fused here
__global__ void scan_block_kernel(int n) {
    __shared__ int sh[SCAN_B];
    int tid = threadIdx.x;
    int i = blockIdx.x * SCAN_B + tid;
    int v = (i < n) ? g_count[i] : 0;
    if (i < n) {
        float deg = (float)(v + 1);        // + self-loop
        g_dinv[i] = rsqrtf(deg);
        g_selfc[i] = 1.0f / deg;
    }
    sh[tid] = v;
    __syncthreads();
#pragma unroll
    for (int off = 1; off < SCAN_B; off <<= 1) {
        int t = (tid >= off) ? sh[tid - off] : 0;
        __syncthreads();
        sh[tid] += t;
        __syncthreads();
    }
    if (i < n) g_rowptr[i] = sh[tid] - v;
    if (tid == SCAN_B - 1) g_bsum[blockIdx.x] = sh[tid];
}

// fused top-level scan + add: each block reduces bsum[0..bid) itself
__global__ void scan_add_kernel(int n, int E) {
    __shared__ int red[SCAN_B];
    int bid = blockIdx.x;
    int tid = threadIdx.x;
    int s = 0;
    for (int j = tid; j < bid; j += SCAN_B) s += g_bsum[j];
    red[tid] = s;
    __syncthreads();
#pragma unroll
    for (int off = SCAN_B / 2; off > 0; off >>= 1) {
        if (tid < off) red[tid] += red[tid + off];
        __syncthreads();
    }
    int boff = red[0];
    int i = bid * SCAN_B + tid;
    if (i < n) {
        int r = g_rowptr[i] + boff;
        g_rowptr[i] = r;
        g_cursor[i] = r;
    }
    if (i == 0) g_rowptr[n] = E;
}

__global__ void fill_kernel(const void* __restrict__ ei, int E) {
    int e = blockIdx.x * blockDim.x + threadIdx.x;
    if (e >= E) return;
    int s, d; load_edge(ei, E, e, s, d);
    float c = g_dinv[s] * g_dinv[d];
    int idx = atomicAdd(&g_cursor[d], 1);
    g_edges[idx] = make_int2(s, __float_as_int(c));
}

// ---------------- layer 1: z = A_norm x  (4-wide gather) ---------------------
__global__ void agg4_kernel(const float* __restrict__ x, float* __restrict__ z, int n) {
    int i = blockIdx.x * blockDim.x + threadIdx.x;
    if (i >= n) return;
    const float4* x4 = (const float4*)x;
    float4 xv = x4[i];
    float sc = g_selfc[i];
    float4 acc = make_float4(xv.x * sc, xv.y * sc, xv.z * sc, xv.w * sc);
    int lo = g_rowptr[i], hi = g_rowptr[i + 1];
    int e = lo;
    for (; e + 4 <= hi; e += 4) {
        int2 e0 = g_edges[e], e1 = g_edges[e+1], e2 = g_edges[e+2], e3 = g_edges[e+3];
        float c0 = __int_as_float(e0.y), c1 = __int_as_float(e1.y);
        float c2 = __int_as_float(e2.y), c3 = __int_as_float(e3.y);
        float4 v0 = __ldg(&x4[e0.x]), v1 = __ldg(&x4[e1.x]);
        float4 v2 = __ldg(&x4[e2.x]), v3 = __ldg(&x4[e3.x]);
        acc.x += c0*v0.x + c1*v1.x + c2*v2.x + c3*v3.x;
        acc.y += c0*v0.y + c1*v1.y + c2*v2.y + c3*v3.y;
        acc.z += c0*v0.z + c1*v1.z + c2*v2.z + c3*v3.z;
        acc.w += c0*v0.w + c1*v1.w + c2*v2.w + c3*v3.w;
    }
    for (; e < hi; e++) {
        int2 ed = g_edges[e];
        float c = __int_as_float(ed.y);
        float4 v = __ldg(&x4[ed.x]);
        acc.x += c*v.x; acc.y += c*v.y; acc.z += c*v.z; acc.w += c*v.w;
    }
    ((float4*)z)[i] = acc;
}

// ---------------- layer 1 matmul: H1 = relu(z @ W1 + b1) -> fp16 -------------
__global__ void mm4_kernel(const float* __restrict__ z, const float* __restrict__ W,
                           const float* __restrict__ b, __half* __restrict__ Hout, int n) {
    __shared__ float Ws[4 * 128 + 128];
    for (int i = threadIdx.x; i < 512; i += blockDim.x) Ws[i] = W[i];
    for (int i = threadIdx.x; i < 128; i += blockDim.x) Ws[512 + i] = b[i];
    __syncthreads();
    int node = blockIdx.x * 2 + (threadIdx.x >> 7);
    if (node >= n) return;
    int f = threadIdx.x & 127;
    float4 zv = ((const float4*)z)[node];
    float acc = Ws[512 + f] + zv.x * Ws[f] + zv.y * Ws[128 + f]
              + zv.z * Ws[256 + f] + zv.w * Ws[384 + f];
    Hout[(size_t)node * 128 + f] = __float2half(fmaxf(acc, 0.f));
}

// ---------------- fp16 mma helper --------------------------------------------
__device__ __forceinline__ void mma_fp16(float& c0, float& c1, float& c2, float& c3,
                                         unsigned a0, unsigned a1, unsigned a2, unsigned a3,
                                         unsigned b0, unsigned b1) {
    asm volatile("mma.sync.aligned.m16n8k16.row.col.f32.f16.f16.f32 "
                 "{%0,%1,%2,%3}, {%4,%5,%6,%7}, {%8,%9}, {%0,%1,%2,%3};"
                 : "+f"(c0), "+f"(c1), "+f"(c2), "+f"(c3)
                 : "r"(a0), "r"(a1), "r"(a2), "r"(a3), "r"(b0), "r"(b1));
}

// ---------------- W prepack (all 3 layers in one kernel) ----------------------
__global__ void prepack_all_kernel(const float* __restrict__ W2,
                                   const float* __restrict__ W3,
                                   const float* __restrict__ W4) {
    int idx = blockIdx.x * blockDim.x + threadIdx.x;
    if (idx >= 3 * 8192) return;
    const float* W = (idx < 8192) ? W2 : (idx < 16384) ? W3 : W4;
    int li   = idx & 8191;
    int r    = li & 1;
    int nt   = (li >> 1) & 3;
    int lane = (li >> 3) & 31;
    int wn   = (li >> 8) & 3;
    int kt   = li >> 10;                   // 0..7
    int k    = 16 * kt + 2 * (lane & 3) + 8 * r;
    int ncol = wn * 32 + nt * 8 + (lane >> 2);
    __half2 h = __floats2half2_rn(W[k * 128 + ncol], W[(k + 1) * 128 + ncol]);
    g_Wph[idx] = *(unsigned*)&h;
}

// ---------------- layers 2..4 matmul: T = Hin(fp16) @ W  (fp16 HMMA) ---------
#define MM_SMEM (128 * 136 * 2 + 8192 * 4)
__global__ void __launch_bounds__(256, 2) mm_tc_kernel(const __half* __restrict__ Hin,
                                                       const unsigned* __restrict__ Wsrc,
                                                       __half* __restrict__ T, int n) {
    extern __shared__ char smem[];
    __half* As = (__half*)smem;
    unsigned* Ws = (unsigned*)(smem + 128 * 136 * 2);

    int tid = threadIdx.x;
    int row0 = blockIdx.x * 128;

    {
        const uint4* H4 = (const uint4*)Hin;        // 16 uint4 per row
        for (int i = tid; i < 128 * 16; i += 256) {
            int r = i >> 4;
            int c = i & 15;
            int gr = row0 + r;
            uint4 v = make_uint4(0u, 0u, 0u, 0u);
            if (gr < n) v = H4[(size_t)gr * 16 + c];
            *(uint4*)(As + r * 136 + c * 8) = v;
        }
        uint4* Wd = (uint4*)Ws;
        const uint4* Wsc = (const uint4*)Wsrc;
        for (int i = tid; i < 2048; i += 256) Wd[i] = Wsc[i];
    }
    __syncthreads();

    int warp = tid >> 5;
    int lane = tid & 31;
    int wm = warp >> 2;            // 0..1
    int wn = warp & 3;             // 0..3

    float acc[4][4][4];
#pragma unroll
    for (int mt = 0; mt < 4; mt++)
#pragma unroll
        for (int nt = 0; nt < 4; nt++)
#pragma unroll
            for (int r = 0; r < 4; r++) acc[mt][nt][r] = 0.f;

    int arow = lane & 15;
    int acol = (lane >> 4) << 3;

    const uint4* WB = (const uint4*)Ws;
#pragma unroll
    for (int kt = 0; kt < 8; kt++) {
        unsigned a[4][4];
#pragma unroll
        for (int mt = 0; mt < 4; mt++) {
            const __half* p = As + (wm * 64 + mt * 16 + arow) * 136 + kt * 16 + acol;
            unsigned addr = (unsigned)__cvta_generic_to_shared(p);
            asm volatile("ldmatrix.sync.aligned.m8n8.x4.shared.b16 {%0,%1,%2,%3}, [%4];"
                         : "=r"(a[mt][0]), "=r"(a[mt][1]), "=r"(a[mt][2]), "=r"(a[mt][3])
                         : "r"(addr));
        }
        int wbase = (((kt * 4 + wn) * 32 + lane) * 8) >> 2;   // uint4 index
        uint4 w0 = WB[wbase];
        uint4 w1 = WB[wbase + 1];
        unsigned b[4][2] = {{w0.x, w0.y}, {w0.z, w0.w}, {w1.x, w1.y}, {w1.z, w1.w}};
#pragma unroll
        for (int mt = 0; mt < 4; mt++)
#pragma unroll
            for (int nt = 0; nt < 4; nt++)
                mma_fp16(acc[mt][nt][0], acc[mt][nt][1], acc[mt][nt][2], acc[mt][nt][3],
                         a[mt][0], a[mt][1], a[mt][2], a[mt][3], b[nt][0], b[nt][1]);
    }

    // epilogue: convert to half2, write T
    int l4 = lane >> 2;
    int lm4 = lane & 3;
#pragma unroll
    for (int mt = 0; mt < 4; mt++) {
        int row = row0 + wm * 64 + mt * 16 + l4;
#pragma unroll
        for (int nt = 0; nt < 4; nt++) {
            int col = wn * 32 + nt * 8 + 2 * lm4;
            if (row < n) {
                __half2 h = __floats2half2_rn(acc[mt][nt][0], acc[mt][nt][1]);
                *(unsigned*)&T[(size_t)row * 128 + col] = *(unsigned*)&h;
            }
            if (row + 8 < n) {
                __half2 h = __floats2half2_rn(acc[mt][nt][2], acc[mt][nt][3]);
                *(unsigned*)&T[(size_t)(row + 8) * 128 + col] = *(unsigned*)&h;
            }
        }
    }
}

// ------- CSR gather: Hout[i] = relu(b + selfc*T[i] + sum coef*T[src]) (fp16) -
// R7-exact structure: 8/4/1 unroll tiers (measured best); __ldg on T reads.
__global__ void gather_kernel(const __half* __restrict__ T, const float* __restrict__ b,
                              __half* __restrict__ Hout, int n) {
    int node = blockIdx.x * 8 + (threadIdx.x >> 5);
    if (node >= n) return;
    int lane = threadIdx.x & 31;
    const uint2* T2 = (const uint2*)T;       // 4 halves per lane; row stride 32

    float4 acc;
    {
        uint2 raw = __ldg(&T2[(size_t)node * 32 + lane]);
        float2 f0 = __half22float2(*(__half2*)&raw.x);
        float2 f1 = __half22float2(*(__half2*)&raw.y);
        float sc = g_selfc[node];
        acc = make_float4(f0.x * sc, f0.y * sc, f1.x * sc, f1.y * sc);
    }

    int lo = g_rowptr[node], hi = g_rowptr[node + 1];
    for (int base = lo; base < hi; base += 32) {
        int e = base + lane;
        int s = 0; float c = 0.f;
        if (e < hi) {
            int2 ed = g_edges[e];
            s = ed.x; c = __int_as_float(ed.y);
        }
        int cnt = min(32, hi - base);
        int j = 0;
        for (; j + 8 <= cnt; j += 8) {
            int sa[8]; float ca[8]; uint2 rw[8];
#pragma unroll
            for (int q = 0; q < 8; q++) {
                sa[q] = __shfl_sync(0xffffffffu, s, j + q);
                ca[q] = __shfl_sync(0xffffffffu, c, j + q);
            }
#pragma unroll
            for (int q = 0; q < 8; q++) rw[q] = __ldg(&T2[(size_t)sa[q] * 32 + lane]);
#pragma unroll
            for (int q = 0; q < 8; q++) {
                float2 f0 = __half22float2(*(__half2*)&rw[q].x);
                float2 f1 = __half22float2(*(__half2*)&rw[q].y);
                acc.x += ca[q] * f0.x; acc.y += ca[q] * f0.y;
                acc.z += ca[q] * f1.x; acc.w += ca[q] * f1.y;
            }
        }
        for (; j + 4 <= cnt; j += 4) {
            int sa[4]; float ca[4]; uint2 rw[4];
#pragma unroll
            for (int q = 0; q < 4; q++) {
                sa[q] = __shfl_sync(0xffffffffu, s, j + q);
                ca[q] = __shfl_sync(0xffffffffu, c, j + q);
            }
#pragma unroll
            for (int q = 0; q < 4; q++) rw[q] = __ldg(&T2[(size_t)sa[q] * 32 + lane]);
#pragma unroll
            for (int q = 0; q < 4; q++) {
                float2 f0 = __half22float2(*(__half2*)&rw[q].x);
                float2 f1 = __half22float2(*(__half2*)&rw[q].y);
                acc.x += ca[q] * f0.x; acc.y += ca[q] * f0.y;
                acc.z += ca[q] * f1.x; acc.w += ca[q] * f1.y;
            }
        }
        for (; j < cnt; j++) {
            int   ss = __shfl_sync(0xffffffffu, s, j);
            float cc = __shfl_sync(0xffffffffu, c, j);
            uint2 r = __ldg(&T2[(size_t)ss * 32 + lane]);
            float2 f0 = __half22float2(*(__half2*)&r.x);
            float2 f1 = __half22float2(*(__half2*)&r.y);
            acc.x += cc*f0.x; acc.y += cc*f0.y; acc.z += cc*f1.x; acc.w += cc*f1.y;
        }
    }
    float4 bv = ((const float4*)b)[lane];
    __half2 h0 = __floats2half2_rn(fmaxf(acc.x + bv.x, 0.f), fmaxf(acc.y + bv.y, 0.f));
    __half2 h1 = __floats2half2_rn(fmaxf(acc.z + bv.z, 0.f), fmaxf(acc.w + bv.w, 0.f));
    uint2 o;
    o.x = *(unsigned*)&h0;
    o.y = *(unsigned*)&h1;
    ((uint2*)Hout)[(size_t)node * 32 + lane] = o;
}

// ---------------- pool (fp16 in, relu'd already) + head ----------------------
__device__ __forceinline__ long long batch_val(const void* b, int i, int is64) {
    return is64 ? ((const long long*)b)[i] : (long long)((const int*)b)[i];
}
__device__ __forceinline__ int lb_batch(const void* b, int n, int is64, long long key) {
    int lo = 0, hi = n;
    while (lo < hi) {
        int mid = (lo + hi) >> 1;
        if (batch_val(b, mid, is64) < key) lo = mid + 1; else hi = mid;
    }
    return lo;
}

__global__ void pool_kernel(const __half* __restrict__ Hf, const void* __restrict__ batch,
                            const float* __restrict__ Wl, const float* __restrict__ bl,
                            float* __restrict__ out, int n) {
    int g = blockIdx.x;
    int is64 = g_batch64;
    int lo = lb_batch(batch, n, is64, (long long)g);
    int hi = lb_batch(batch, n, is64, (long long)g + 1);
    int f = threadIdx.x;              // 0..63, handles half2 pair

    float2 sum = make_float2(0.f, 0.f);
    const __half2* H2 = (const __half2*)Hf;
    for (int i = lo; i < hi; i++) {
        float2 v = __half22float2(H2[(size_t)i * 64 + f]);
        sum.x += v.x; sum.y += v.y;
    }

    float cnt = (float)((hi - lo) > 0 ? (hi - lo) : 1);
    __shared__ float sp[128];
    sp[2 * f]     = sum.x / cnt;
    sp[2 * f + 1] = sum.y / cnt;
    __syncthreads();

    if (f < 5) {
        float a = bl[f];
#pragma unroll 8
        for (int k = 0; k < 128; k++) a += sp[k] * Wl[k * 5 + f];
        out[g * 5 + f] = 1.f / (1.f + expf(-a));
    }
}

// ---------------- launch -----------------------------------------------------
extern "C" void kernel_launch(void* const* d_in, const int* in_sizes, int n_in,
                              void* d_out, int out_size) {
    const float* x  = (const float*)d_in[0];
    const void*  ei = d_in[1];
    const void*  bt = d_in[2];
    const float* W1 = (const float*)d_in[3];
    const float* b1 = (const float*)d_in[4];
    const float* W2 = (const float*)d_in[5];
    const float* b2 = (const float*)d_in[6];
    const float* W3 = (const float*)d_in[7];
    const float* b3 = (const float*)d_in[8];
    const float* W4 = (const float*)d_in[9];
    const float* b4 = (const float*)d_in[10];
    const float* Wl = (const float*)d_in[11];
    const float* bl = (const float*)d_in[12];
    float* out = (float*)d_out;

    int n  = in_sizes[0] / 4;
    int E  = in_sizes[1] / 2;
    int nb = in_sizes[2];
    int G  = out_size / 5;

    float *Tf, *Af, *Bf;
    cudaGetSymbolAddress((void**)&Tf, g_T);
    cudaGetSymbolAddress((void**)&Af, g_A);
    cudaGetSymbolAddress((void**)&Bf, g_B);
    unsigned* Wp;
    cudaGetSymbolAddress((void**)&Wp, g_Wph);
    __half* Th = (__half*)Tf;
    __half* Ah = (__half*)Af;
    __half* Bh = (__half*)Bf;

    cudaFuncSetAttribute(mm_tc_kernel, cudaFuncAttributeMaxDynamicSharedMemorySize, MM_SMEM);

    const int TB = 256;
    int gN  = (n + TB - 1) / TB;
    int gE  = (E + TB - 1) / TB;
    int gMM = (n + 127) / 128;
    int gGA = (n + 7) / 8;
    int nblk = (n + SCAN_B - 1) / SCAN_B;
    int n4  = (n + 3) / 4;

    // prep + CSR build
    detect_kernel<<<1, 32>>>((const int*)ei, (const int*)bt, nb);
    prepack_all_kernel<<<96, 256>>>(W2, W3, W4);
    count_init_kernel<<<(n4 + TB - 1) / TB, TB>>>(n4);
    count_kernel<<<gE, TB>>>(ei, E);
    scan_block_kernel<<<nblk, SCAN_B>>>(n);
    scan_add_kernel<<<nblk, SCAN_B>>>(n, E);
    fill_kernel<<<gE, TB>>>(ei, E);

    // layer 1: aggregate x first (4-wide), then mm4 -> relu'd fp16 H1
    agg4_kernel<<<gN, TB>>>(x, Tf, n);          // z lives in g_T temporarily (fp32)
    mm4_kernel<<<(n + 1) / 2, TB>>>(Tf, W1, b1, Ah, n);

    // layers 2..4: fp16 tensor-core mm + fp16 CSR gather (bias+relu fused)
    mm_tc_kernel<<<gMM, TB, MM_SMEM>>>(Ah, Wp, Th, n);
    gather_kernel<<<gGA, TB>>>(Th, b2, Bh, n);

    mm_tc_kernel<<<gMM, TB, MM_SMEM>>>(Bh, Wp + 8192, Th, n);
    gather_kernel<<<gGA, TB>>>(Th, b3, Ah, n);

    mm_tc_kernel<<<gMM, TB, MM_SMEM>>>(Ah, Wp + 16384, Th, n);
    gather_kernel<<<gGA, TB>>>(Th, b4, Bh, n);

    // pool (mean of relu'd fp16 H4) + head
    pool_kernel<<<G, 64>>>(Bh, bt, Wl, bl, out, n);
}